// round 13
// baseline (speedup 1.0000x reference)
#include <cuda_runtime.h>
#include <stdint.h>

// Inputs (metadata order):
//   d_in[0] disp        float32 [E,3]   (E = 3,200,000)
//   d_in[1] a           float32 [E]
//   d_in[2] b           float32 [E]
//   d_in[3] edge_index  int32   [2,E]   row0 = src, row1 = dst
//   d_in[4] atom_node   int32   [N]     (N = 100,000)
// Output: float32 [N,3]
//
// force_edge = 2*(b*exp(-r2) - a) * disp ;  out = scatter(+,src) - scatter(+,dst)
//
// Single persistent kernel (one graph node):
//   phase 0: grid-stride zero of g_accum
//   barrier
//   phase 1: grid-stride edge scatter, 2 x RED.128 per edge (algorithmic floor)
//   barrier
//   phase 2: grid-stride gather [N,4] -> [N,3] via __ldcg
//
// Grid = exactly one co-resident wave (occupancy query x SM count, computed
// every call). Sense-reversing grid barrier; count/sense state self-restores
// after the 2 barriers, so every graph replay starts from identical state.

#define N_MAX 100352  // >= 100000

__device__ float4 g_accum[N_MAX];
__device__ unsigned int g_bar_count = 0;  // .bss zero at load
__device__ unsigned int g_bar_sense = 0;

__device__ __forceinline__ void grid_barrier(unsigned int* local_sense) {
    unsigned int want = 1u - *local_sense;
    *local_sense = want;
    __syncthreads();
    if (threadIdx.x == 0) {
        __threadfence();  // make this block's stores/REDs globally visible
        unsigned int old = atomicAdd(&g_bar_count, 1u);
        if (old == gridDim.x - 1u) {
            g_bar_count = 0;            // all arrived; safe before sense release
            __threadfence();
            atomicExch(&g_bar_sense, want);  // release
        } else {
            while (atomicAdd(&g_bar_sense, 0u) != want) { __nanosleep(64); }
        }
    }
    __syncthreads();
}

__global__ __launch_bounds__(256)
void fused_force_kernel(const float* __restrict__ disp,
                        const float* __restrict__ a,
                        const float* __restrict__ b,
                        const int* __restrict__ src,
                        const int* __restrict__ dst,
                        float* __restrict__ out,
                        int num_edges, int n_atoms) {
    unsigned int local_sense = 0;
    const int tid = blockIdx.x * blockDim.x + threadIdx.x;
    const int nth = gridDim.x * blockDim.x;

    // Phase 0: zero the accumulator (full float4 stores, coalesced).
    for (int i = tid; i < n_atoms; i += nth)
        g_accum[i] = make_float4(0.f, 0.f, 0.f, 0.f);

    grid_barrier(&local_sense);

    // Phase 1: edge scatter.
    for (int e = tid; e < num_edges; e += nth) {
        float dx = disp[3 * e + 0];
        float dy = disp[3 * e + 1];
        float dz = disp[3 * e + 2];
        float r2 = fmaf(dx, dx, fmaf(dy, dy, dz * dz));

        float ae = a[e];
        float be = b[e];
        float s = 2.0f * fmaf(be, __expf(-r2), -ae);  // 2*(b*exp(-r2) - a)

        float fx = s * dx, fy = s * dy, fz = s * dz;

        int si = src[e];
        int di = dst[e];

        atomicAdd(&g_accum[si], make_float4( fx,  fy,  fz, 0.f));
        atomicAdd(&g_accum[di], make_float4(-fx, -fy, -fz, 0.f));
    }

    grid_barrier(&local_sense);

    // Phase 2: gather [N,4] -> [N,3]. __ldcg: read from L2 (atomic results).
    for (int i = tid; i < n_atoms; i += nth) {
        float4 v = __ldcg(&g_accum[i]);
        out[3 * i + 0] = v.x;
        out[3 * i + 1] = v.y;
        out[3 * i + 2] = v.z;
    }
}

extern "C" void kernel_launch(void* const* d_in, const int* in_sizes, int n_in,
                              void* d_out, int out_size) {
    const float* disp = (const float*)d_in[0];
    const float* a    = (const float*)d_in[1];
    const float* b    = (const float*)d_in[2];
    const int*   ei   = (const int*)d_in[3];   // int32 [2, E]

    int num_edges = in_sizes[1];               // a is [E]
    const int* src = ei;
    const int* dst = ei + num_edges;

    float* out = (float*)d_out;
    int n_atoms = out_size / 3;

    // Exactly one co-resident wave (deterministic: same result every call).
    int dev = 0;
    cudaGetDevice(&dev);
    int sm_count = 0;
    cudaDeviceGetAttribute(&sm_count, cudaDevAttrMultiProcessorCount, dev);
    int blocks_per_sm = 0;
    cudaOccupancyMaxActiveBlocksPerMultiprocessor(&blocks_per_sm,
                                                  fused_force_kernel, 256, 0);
    if (blocks_per_sm < 1) blocks_per_sm = 1;
    int grid = sm_count * blocks_per_sm;
    // Never launch more blocks than one wave; barrier requires co-residency.

    fused_force_kernel<<<grid, 256>>>(disp, a, b, src, dst, out,
                                      num_edges, n_atoms);
}

// round 15
// speedup vs baseline: 1.7828x; 1.7828x over previous
#include <cuda_runtime.h>
#include <stdint.h>

// Inputs (metadata order):
//   d_in[0] disp        float32 [E,3]   (E = 3,200,000)
//   d_in[1] a           float32 [E]
//   d_in[2] b           float32 [E]
//   d_in[3] edge_index  int32   [2,E]   row0 = src, row1 = dst
//   d_in[4] atom_node   int32   [N]     (N = 100,000)
// Output: float32 [N,3]
//
// force_edge = 2*(b*exp(-r2) - a) * disp ;  out = scatter(+,src) - scatter(+,dst)
//
// Pipeline (proven-fast composition, R10):
//   memset node (zeros g_accum) ->
//   1-edge/thread scatter, 2 x RED.128 per edge (at the REDG lane-rate floor) ->
//   1-thread/output-float gather (max parallelism, fully coalesced stores).

#define N_MAX 100352  // >= 100000

__device__ float4 g_accum[N_MAX];

__global__ __launch_bounds__(256)
void edge_force_scatter_kernel(const float* __restrict__ disp,
                               const float* __restrict__ a,
                               const float* __restrict__ b,
                               const int* __restrict__ src,
                               const int* __restrict__ dst,
                               int num_edges) {
    int e = blockIdx.x * blockDim.x + threadIdx.x;
    if (e >= num_edges) return;

    float dx = disp[3 * e + 0];
    float dy = disp[3 * e + 1];
    float dz = disp[3 * e + 2];
    float r2 = fmaf(dx, dx, fmaf(dy, dy, dz * dz));

    float ae = a[e];
    float be = b[e];
    float s = 2.0f * fmaf(be, __expf(-r2), -ae);  // 2*(b*exp(-r2) - a)

    float fx = s * dx, fy = s * dy, fz = s * dz;

    int si = src[e];
    int di = dst[e];

    atomicAdd(&g_accum[si], make_float4( fx,  fy,  fz, 0.f));
    atomicAdd(&g_accum[di], make_float4(-fx, -fy, -fz, 0.f));
}

// One thread per output float: out[idx] = accum[idx/3].{x,y,z}[idx%3].
// 300k threads, coalesced STG.32, one scalar __ldcg each.
__global__ __launch_bounds__(256)
void gather_out_kernel(float* __restrict__ out, int n3) {
    int idx = blockIdx.x * blockDim.x + threadIdx.x;
    if (idx >= n3) return;
    int i = idx / 3;           // atom row
    int c = idx - 3 * i;       // component 0..2
    const float* acc = (const float*)g_accum;
    out[idx] = __ldcg(acc + 4 * i + c);
}

extern "C" void kernel_launch(void* const* d_in, const int* in_sizes, int n_in,
                              void* d_out, int out_size) {
    const float* disp = (const float*)d_in[0];
    const float* a    = (const float*)d_in[1];
    const float* b    = (const float*)d_in[2];
    const int*   ei   = (const int*)d_in[3];   // int32 [2, E]

    int num_edges = in_sizes[1];               // a is [E]
    const int* src = ei;
    const int* dst = ei + num_edges;

    float* out = (float*)d_out;
    int n_atoms = out_size / 3;

    // Zero the accumulator (graph-capturable memset node).
    void* accum_ptr = nullptr;
    cudaGetSymbolAddress(&accum_ptr, g_accum);
    cudaMemsetAsync(accum_ptr, 0, (size_t)n_atoms * sizeof(float4));

    {
        int threads = 256;
        int blocks = (num_edges + threads - 1) / threads;
        edge_force_scatter_kernel<<<blocks, threads>>>(disp, a, b, src, dst,
                                                       num_edges);
    }
    {
        int threads = 256;
        int n3 = out_size;  // 3 * n_atoms
        int blocks = (n3 + threads - 1) / threads;
        gather_out_kernel<<<blocks, threads>>>(out, n3);
    }
}

// round 16
// speedup vs baseline: 1.8726x; 1.0503x over previous
#include <cuda_runtime.h>
#include <stdint.h>

// Inputs (metadata order):
//   d_in[0] disp        float32 [E,3]   (E = 3,200,000)
//   d_in[1] a           float32 [E]
//   d_in[2] b           float32 [E]
//   d_in[3] edge_index  int32   [2,E]   row0 = src, row1 = dst
//   d_in[4] atom_node   int32   [N]     (N = 100,000)
// Output: float32 [N,3]
//
// force_edge = 2*(b*exp(-r2) - a) * disp ;  out = scatter(+,src) - scatter(+,dst)
//
// Pipeline with PDL (programmatic dependent launch) overlap:
//   zero_accum --PDL--> scatter --PDL--> gather
// Secondary kernels launch early, run their independent prologue (input loads /
// index math), then cudaGridDependencySynchronize() before touching the
// dependent data. Scatter stays 2 x RED.128/edge (measured at the REDG floor).

#define N_MAX 100352  // >= 100000

__device__ float4 g_accum[N_MAX];

__global__ __launch_bounds__(256)
void zero_accum_kernel(int n) {
    int i = blockIdx.x * blockDim.x + threadIdx.x;
    if (i < n) g_accum[i] = make_float4(0.f, 0.f, 0.f, 0.f);
}

__global__ __launch_bounds__(256)
void edge_force_scatter_kernel(const float* __restrict__ disp,
                               const float* __restrict__ a,
                               const float* __restrict__ b,
                               const int* __restrict__ src,
                               const int* __restrict__ dst,
                               int num_edges) {
    int e = blockIdx.x * blockDim.x + threadIdx.x;
    if (e >= num_edges) {
        cudaGridDependencySynchronize();
        return;
    }

    // Prologue: all loads are independent of g_accum -> overlap with zeroing.
    float dx = disp[3 * e + 0];
    float dy = disp[3 * e + 1];
    float dz = disp[3 * e + 2];
    float ae = a[e];
    float be = b[e];
    int si = src[e];
    int di = dst[e];

    float r2 = fmaf(dx, dx, fmaf(dy, dy, dz * dz));
    float s = 2.0f * fmaf(be, __expf(-r2), -ae);  // 2*(b*exp(-r2) - a)
    float fx = s * dx, fy = s * dy, fz = s * dz;

    // Wait until the zero kernel's stores are complete & visible.
    cudaGridDependencySynchronize();

    atomicAdd(&g_accum[si], make_float4( fx,  fy,  fz, 0.f));
    atomicAdd(&g_accum[di], make_float4(-fx, -fy, -fz, 0.f));
}

// One thread per output float: out[idx] = accum[idx/3].{x,y,z}[idx%3].
__global__ __launch_bounds__(256)
void gather_out_kernel(float* __restrict__ out, int n3) {
    int idx = blockIdx.x * blockDim.x + threadIdx.x;
    int i = idx / 3;           // atom row
    int c = idx - 3 * i;       // component 0..2
    const float* acc = (const float*)g_accum;

    // Wait for all scatter REDs to complete & be visible.
    cudaGridDependencySynchronize();

    if (idx < n3) out[idx] = __ldcg(acc + 4 * i + c);
}

static void launch_pdl(void* func, dim3 grid, dim3 block,
                       void** args, cudaStream_t stream) {
    cudaLaunchConfig_t cfg = {};
    cfg.gridDim = grid;
    cfg.blockDim = block;
    cfg.dynamicSmemBytes = 0;
    cfg.stream = stream;
    cudaLaunchAttribute attr[1];
    attr[0].id = cudaLaunchAttributeProgrammaticStreamSerialization;
    attr[0].val.programmaticStreamSerializationAllowed = 1;
    cfg.attrs = attr;
    cfg.numAttrs = 1;
    cudaLaunchKernelExC(&cfg, func, args);
}

extern "C" void kernel_launch(void* const* d_in, const int* in_sizes, int n_in,
                              void* d_out, int out_size) {
    const float* disp = (const float*)d_in[0];
    const float* a    = (const float*)d_in[1];
    const float* b    = (const float*)d_in[2];
    const int*   ei   = (const int*)d_in[3];   // int32 [2, E]

    int num_edges = in_sizes[1];               // a is [E]
    const int* src = ei;
    const int* dst = ei + num_edges;

    float* out = (float*)d_out;
    int n_atoms = out_size / 3;
    cudaStream_t stream = 0;  // legacy default stream (harness captures it)

    // 1) Zero accumulator (plain launch).
    {
        int threads = 256;
        int blocks = (n_atoms + threads - 1) / threads;
        zero_accum_kernel<<<blocks, threads>>>(n_atoms);
    }

    // 2) Scatter with PDL: overlaps its input-load prologue with the zeroing.
    {
        int threads = 256;
        int blocks = (num_edges + threads - 1) / threads;
        void* args[] = {(void*)&disp, (void*)&a, (void*)&b,
                        (void*)&src, (void*)&dst, (void*)&num_edges};
        launch_pdl((void*)edge_force_scatter_kernel,
                   dim3(blocks), dim3(threads), args, stream);
    }

    // 3) Gather with PDL: overlaps its launch ramp with the scatter tail.
    {
        int threads = 256;
        int n3 = out_size;  // 3 * n_atoms
        int blocks = (n3 + threads - 1) / threads;
        void* args[] = {(void*)&out, (void*)&n3};
        launch_pdl((void*)gather_out_kernel,
                   dim3(blocks), dim3(threads), args, stream);
    }
}